// round 11
// baseline (speedup 1.0000x reference)
#include <cuda_runtime.h>

#define N_IN       1024
#define BATCH      1024
#define DEG        32
#define TOTAL_COLS 18432
#define N_OUT      1024

// Unified int16 Q buffer, column-major: cols 0..1023 quantized input,
// cols 1024.. tanh outputs. 37.7 MB.
__device__ short g_q[(size_t)TOTAL_COLS * BATCH];
// fp32 col-major staging for X (4 MB) + max|X| bits.
__device__ float g_stage[N_IN * BATCH];
__device__ unsigned g_maxbits;

// PDL intrinsics (sm_90+)
__device__ __forceinline__ void pdl_wait() {
    asm volatile("griddepcontrol.wait;" ::: "memory");
}
__device__ __forceinline__ void pdl_launch_dependents() {
    asm volatile("griddepcontrol.launch_dependents;" ::: "memory");
}

// Deterministic scale from max bits (identical in every block).
__device__ __forceinline__ float scale_from_bits(unsigned mb) {
    float m = __uint_as_float(mb);
    if (m < 1.0f) m = 1.0f;           // tanh outputs (|v|<1) must also fit
    return 32000.0f / m;
}

__global__ void init_kernel() { g_maxbits = 0u; }

// ---------------------------------------------------------------------------
// Fused transpose + max: block handles 4 stacked 32x32 tiles (front-batched
// 16 LDGs/thread for MLP). X (row-major) -> g_stage (col-major fp32),
// atomicMax(g_maxbits). grid 256, block (32,8).
// ---------------------------------------------------------------------------
__global__ void transpose_max_kernel(const float* __restrict__ X) {
    __shared__ float tile[32][33];
    const int tx = threadIdx.x, ty = threadIdx.y;
    const int bx  = (blockIdx.x & 31) * 32;   // feature tile base
    const int by0 = (blockIdx.x >> 5) * 128;  // batch super-tile base (4 tiles)

    float v[4][4];
    #pragma unroll
    for (int r = 0; r < 4; r++)
        #pragma unroll
        for (int i = 0; i < 4; i++)
            v[r][i] = X[(by0 + r * 32 + ty + i * 8) * N_IN + (bx + tx)];

    float m = 0.f;
    #pragma unroll
    for (int r = 0; r < 4; r++)
        #pragma unroll
        for (int i = 0; i < 4; i++)
            m = fmaxf(m, fabsf(v[r][i]));
    #pragma unroll
    for (int o = 16; o; o >>= 1)
        m = fmaxf(m, __shfl_xor_sync(0xFFFFFFFFu, m, o));

    pdl_wait();                        // init_kernel zeroed g_maxbits
    if (tx == 0)
        atomicMax(&g_maxbits, __float_as_uint(m));  // non-neg: bit order = value order

    #pragma unroll
    for (int r = 0; r < 4; r++) {
        __syncthreads();
        #pragma unroll
        for (int i = 0; i < 4; i++)
            tile[ty + i * 8][tx] = v[r][i];
        __syncthreads();
        #pragma unroll
        for (int i = 0; i < 4; i++)
            g_stage[(size_t)(bx + ty + i * 8) * BATCH + (by0 + r * 32 + tx)] =
                tile[tx][ty + i * 8];
    }
    pdl_launch_dependents();           // maxes + staging visible to quantize
}

// ---------------------------------------------------------------------------
// Quantize staging (L2-hot) -> g_q cols 0..1023. Elementwise, layout-
// preserving, vectorized. grid 128, block 256: 8 float4 per thread.
// ---------------------------------------------------------------------------
__global__ void __launch_bounds__(256) quantize_kernel() {
    pdl_wait();                        // all maxes + staging complete
    const float s = scale_from_bits(g_maxbits);
    const float4* src = reinterpret_cast<const float4*>(g_stage);
    short4* dst = reinterpret_cast<short4*>(g_q);
    int i = blockIdx.x * 256 + threadIdx.x;
    #pragma unroll
    for (int r = 0; r < 8; r++, i += 128 * 256) {
        float4 v = src[i];
        short4 o;
        o.x = (short)__float2int_rn(v.x * s);
        o.y = (short)__float2int_rn(v.y * s);
        o.z = (short)__float2int_rn(v.z * s);
        o.w = (short)__float2int_rn(v.w * s);
        dst[i] = o;
    }
    pdl_launch_dependents();
}

// ---------------------------------------------------------------------------
// Gather core: 128 threads, thread t owns batch elems 8t..8t+7 (one uint4 =
// 8 int16). Exact integer accumulation via DP2A.
// ---------------------------------------------------------------------------
__device__ __forceinline__ void gather_sum(const int* __restrict__ sidx, int t,
                                           int acc[8]) {
    const uint4* q4 = reinterpret_cast<const uint4*>(g_q);
    int a0=0,a1=0,a2=0,a3=0,a4=0,a5=0,a6=0,a7=0;
    #pragma unroll
    for (int k = 0; k < DEG; k++) {
        uint4 v = q4[(size_t)sidx[k] * (BATCH / 8) + t];
        a0 = __dp2a_lo((int)v.x, 0x0001, a0);
        a1 = __dp2a_lo((int)v.x, 0x0100, a1);
        a2 = __dp2a_lo((int)v.y, 0x0001, a2);
        a3 = __dp2a_lo((int)v.y, 0x0100, a3);
        a4 = __dp2a_lo((int)v.z, 0x0001, a4);
        a5 = __dp2a_lo((int)v.z, 0x0100, a5);
        a6 = __dp2a_lo((int)v.w, 0x0001, a6);
        a7 = __dp2a_lo((int)v.w, 0x0100, a7);
    }
    acc[0]=a0; acc[1]=a1; acc[2]=a2; acc[3]=a3;
    acc[4]=a4; acc[5]=a5; acc[6]=a6; acc[7]=a7;
}

// ---------------------------------------------------------------------------
// Layers 1..8: index load overlaps predecessor tail (PDL); dependents
// released right after the column store.
// ---------------------------------------------------------------------------
__global__ void __launch_bounds__(128) layer_kernel(
    const int* __restrict__ child_idx, const float* __restrict__ w_ptr,
    int col_base)
{
    const int j = blockIdx.x, t = threadIdx.x;
    __shared__ int sidx[DEG];
    if (t < DEG) sidx[t] = child_idx[j * DEG + t];   // input-only: pre-wait OK
    __syncthreads();
    pdl_wait();                        // predecessor's g_q writes visible

    int a[8];
    gather_sum(sidx, t, a);

    const float s  = scale_from_bits(g_maxbits);     // flushed at gpu scope
    const float ws = __ldg(w_ptr) / s;

    int q[8];
    #pragma unroll
    for (int i = 0; i < 8; i++)
        q[i] = __float2int_rn(tanhf(ws * (float)a[i]) * s);

    uint4 o;
    o.x = (q[0] & 0xFFFF) | (q[1] << 16);
    o.y = (q[2] & 0xFFFF) | (q[3] << 16);
    o.z = (q[4] & 0xFFFF) | (q[5] << 16);
    o.w = (q[6] & 0xFFFF) | (q[7] << 16);
    reinterpret_cast<uint4*>(g_q)[(size_t)(col_base + j) * (BATCH / 8) + t] = o;

    pdl_launch_dependents();
}

// ---------------------------------------------------------------------------
// Layer 9: outputs never gathered -> write fp32 straight to d_out (row-major).
// ---------------------------------------------------------------------------
__global__ void __launch_bounds__(128) last_layer_kernel(
    const int* __restrict__ child_idx, const float* __restrict__ w_ptr,
    float* __restrict__ out)
{
    const int j = blockIdx.x, t = threadIdx.x;
    __shared__ int sidx[DEG];
    if (t < DEG) sidx[t] = child_idx[j * DEG + t];
    __syncthreads();
    pdl_wait();

    int a[8];
    gather_sum(sidx, t, a);

    const float s  = scale_from_bits(g_maxbits);
    const float ws = __ldg(w_ptr) / s;

    #pragma unroll
    for (int i = 0; i < 8; i++)
        out[(size_t)(8 * t + i) * N_OUT + j] = tanhf(ws * (float)a[i]);
}

// ---------------------------------------------------------------------------
// Host-side PDL launch helper.
// ---------------------------------------------------------------------------
template <typename... Args>
static void launch_pdl(void (*kern)(Args...), dim3 grid, dim3 block,
                       Args... args) {
    cudaLaunchConfig_t cfg = {};
    cfg.gridDim = grid;
    cfg.blockDim = block;
    cfg.dynamicSmemBytes = 0;
    cfg.stream = 0;
    cudaLaunchAttribute attr[1];
    attr[0].id = cudaLaunchAttributeProgrammaticStreamSerialization;
    attr[0].val.programmaticStreamSerializationAllowed = 1;
    cfg.attrs = attr;
    cfg.numAttrs = 1;
    cudaLaunchKernelEx(&cfg, kern, args...);
}

extern "C" void kernel_launch(void* const* d_in, const int* in_sizes, int n_in,
                              void* d_out, int out_size) {
    const float* X         = (const float*)d_in[0];
    const float* w         = (const float*)d_in[1];
    const int*   child_idx = (const int*)d_in[2];
    float*       out       = (float*)d_out;
    (void)in_sizes; (void)n_in; (void)out_size;

    init_kernel<<<1, 1>>>();
    launch_pdl(transpose_max_kernel, dim3(256), dim3(32, 8), X);
    launch_pdl(quantize_kernel, dim3(128), dim3(256));

    int idx_base = 0;
    int col_base = N_IN;
    for (int li = 0; li < 8; li++) {
        launch_pdl(layer_kernel, dim3(2048), dim3(128),
                   (const int*)(child_idx + (size_t)idx_base * DEG), w, col_base);
        idx_base += 2048;
        col_base += 2048;
    }
    launch_pdl(last_layer_kernel, dim3(1024), dim3(128),
               (const int*)(child_idx + (size_t)idx_base * DEG), w, out);
}

// round 12
// speedup vs baseline: 1.1824x; 1.1824x over previous
#include <cuda_runtime.h>

#define N_IN       1024
#define BATCH      1024
#define DEG        32
#define TOTAL_COLS 18432
#define N_OUT      1024

// Unified int16 Q buffer, column-major: cols 0..1023 quantized input,
// cols 1024.. tanh outputs. Single dynamic scale g_s. 37.7 MB.
__device__ short g_q[(size_t)TOTAL_COLS * BATCH];
__device__ unsigned g_maxbits;
__device__ float g_s, g_is;

// PDL intrinsics (sm_90+)
__device__ __forceinline__ void pdl_wait() {
    asm volatile("griddepcontrol.wait;" ::: "memory");
}
__device__ __forceinline__ void pdl_launch_dependents() {
    asm volatile("griddepcontrol.launch_dependents;" ::: "memory");
}

__global__ void init_kernel() { g_maxbits = 0u; }

__global__ void maxabs_kernel(const float* __restrict__ X) {
    const float4* X4 = reinterpret_cast<const float4*>(X);
    float m = 0.f;
    for (int i = blockIdx.x * 256 + threadIdx.x; i < (N_IN * BATCH) / 4;
         i += gridDim.x * 256) {
        float4 v = X4[i];
        m = fmaxf(m, fmaxf(fmaxf(fabsf(v.x), fabsf(v.y)),
                           fmaxf(fabsf(v.z), fabsf(v.w))));
    }
    #pragma unroll
    for (int o = 16; o; o >>= 1)
        m = fmaxf(m, __shfl_xor_sync(0xFFFFFFFFu, m, o));
    if ((threadIdx.x & 31) == 0)
        atomicMax(&g_maxbits, __float_as_uint(m));  // non-neg floats: bit order = value order
}

__global__ void scale_kernel() {
    float m = __uint_as_float(g_maxbits);
    if (m < 1.0f) m = 1.0f;          // tanh outputs (|v|<1) must also fit
    float s = 32000.0f / m;
    g_s = s;
    g_is = 1.0f / s;
}

// ---------------------------------------------------------------------------
// Transpose X -> g_q cols 0..1023 (int16). PDL: X read overlaps scale tail;
// g_s read only after wait. Signals dependents after stores.
// ---------------------------------------------------------------------------
__global__ void transpose_in_kernel(const float* __restrict__ X) {
    __shared__ float tile[32][33];
    int bx = blockIdx.x * 32, by = blockIdx.y * 32;
    int tx = threadIdx.x, ty = threadIdx.y;
    #pragma unroll
    for (int i = 0; i < 32; i += 8)
        tile[ty + i][tx] = X[(by + ty + i) * N_IN + (bx + tx)];
    __syncthreads();
    pdl_wait();                       // g_s valid after scale_kernel completes
    const float s = g_s;
    #pragma unroll
    for (int i = 0; i < 32; i += 8)
        g_q[(size_t)(bx + ty + i) * BATCH + (by + tx)] =
            (short)__float2int_rn(tile[tx][ty + i] * s);
    pdl_launch_dependents();
}

// ---------------------------------------------------------------------------
// Gather core: 128 threads, thread t owns batch elems 8t..8t+7 (one uint4 =
// 8 int16). Exact integer accumulation via DP2A.
// ---------------------------------------------------------------------------
__device__ __forceinline__ void gather_sum(const int* __restrict__ sidx, int t,
                                           int acc[8]) {
    const uint4* q4 = reinterpret_cast<const uint4*>(g_q);
    int a0=0,a1=0,a2=0,a3=0,a4=0,a5=0,a6=0,a7=0;
    #pragma unroll
    for (int k = 0; k < DEG; k++) {
        uint4 v = q4[(size_t)sidx[k] * (BATCH / 8) + t];
        a0 = __dp2a_lo((int)v.x, 0x0001, a0);
        a1 = __dp2a_lo((int)v.x, 0x0100, a1);
        a2 = __dp2a_lo((int)v.y, 0x0001, a2);
        a3 = __dp2a_lo((int)v.y, 0x0100, a3);
        a4 = __dp2a_lo((int)v.z, 0x0001, a4);
        a5 = __dp2a_lo((int)v.z, 0x0100, a5);
        a6 = __dp2a_lo((int)v.w, 0x0001, a6);
        a7 = __dp2a_lo((int)v.w, 0x0100, a7);
    }
    acc[0]=a0; acc[1]=a1; acc[2]=a2; acc[3]=a3;
    acc[4]=a4; acc[5]=a5; acc[6]=a6; acc[7]=a7;
}

// ---------------------------------------------------------------------------
// Layers 1..8: preamble (index load) overlaps predecessor tail via PDL;
// dependents released right after the column store.
// ---------------------------------------------------------------------------
__global__ void __launch_bounds__(128) layer_kernel(
    const int* __restrict__ child_idx, const float* __restrict__ w_ptr,
    int col_base)
{
    const int j = blockIdx.x, t = threadIdx.x;
    __shared__ int sidx[DEG];
    if (t < DEG) sidx[t] = child_idx[j * DEG + t];   // input-only: pre-wait OK
    __syncthreads();
    pdl_wait();                        // predecessor's g_q writes now visible

    int a[8];
    gather_sum(sidx, t, a);

    const float w = __ldg(w_ptr), is = g_is, s = g_s;
    const float ws = w * is;

    int q[8];
    #pragma unroll
    for (int i = 0; i < 8; i++)
        q[i] = __float2int_rn(tanhf(ws * (float)a[i]) * s);

    uint4 o;
    o.x = (q[0] & 0xFFFF) | (q[1] << 16);
    o.y = (q[2] & 0xFFFF) | (q[3] << 16);
    o.z = (q[4] & 0xFFFF) | (q[5] << 16);
    o.w = (q[6] & 0xFFFF) | (q[7] << 16);
    reinterpret_cast<uint4*>(g_q)[(size_t)(col_base + j) * (BATCH / 8) + t] = o;

    pdl_launch_dependents();           // release next layer before block exit
}

// ---------------------------------------------------------------------------
// Layer 9: outputs never gathered -> write fp32 straight to d_out (row-major).
// ---------------------------------------------------------------------------
__global__ void __launch_bounds__(128) last_layer_kernel(
    const int* __restrict__ child_idx, const float* __restrict__ w_ptr,
    float* __restrict__ out)
{
    const int j = blockIdx.x, t = threadIdx.x;
    __shared__ int sidx[DEG];
    if (t < DEG) sidx[t] = child_idx[j * DEG + t];
    __syncthreads();
    pdl_wait();

    int a[8];
    gather_sum(sidx, t, a);

    const float w = __ldg(w_ptr), is = g_is;
    const float ws = w * is;

    #pragma unroll
    for (int i = 0; i < 8; i++)
        out[(size_t)(8 * t + i) * N_OUT + j] = tanhf(ws * (float)a[i]);
}

// ---------------------------------------------------------------------------
// Host-side PDL launch helper.
// ---------------------------------------------------------------------------
template <typename... Args>
static void launch_pdl(void (*kern)(Args...), dim3 grid, dim3 block,
                       Args... args) {
    cudaLaunchConfig_t cfg = {};
    cfg.gridDim = grid;
    cfg.blockDim = block;
    cfg.dynamicSmemBytes = 0;
    cfg.stream = 0;
    cudaLaunchAttribute attr[1];
    attr[0].id = cudaLaunchAttributeProgrammaticStreamSerialization;
    attr[0].val.programmaticStreamSerializationAllowed = 1;
    cfg.attrs = attr;
    cfg.numAttrs = 1;
    cudaLaunchKernelEx(&cfg, kern, args...);
}

extern "C" void kernel_launch(void* const* d_in, const int* in_sizes, int n_in,
                              void* d_out, int out_size) {
    const float* X         = (const float*)d_in[0];
    const float* w         = (const float*)d_in[1];
    const int*   child_idx = (const int*)d_in[2];
    float*       out       = (float*)d_out;
    (void)in_sizes; (void)n_in; (void)out_size;

    init_kernel<<<1, 1>>>();
    maxabs_kernel<<<64, 256>>>(X);
    scale_kernel<<<1, 1>>>();

    launch_pdl(transpose_in_kernel, dim3(32, 32), dim3(32, 8), X);

    int idx_base = 0;
    int col_base = N_IN;
    for (int li = 0; li < 8; li++) {
        launch_pdl(layer_kernel, dim3(2048), dim3(128),
                   (const int*)(child_idx + (size_t)idx_base * DEG), w, col_base);
        idx_base += 2048;
        col_base += 2048;
    }
    launch_pdl(last_layer_kernel, dim3(1024), dim3(128),
               (const int*)(child_idx + (size_t)idx_base * DEG), w, out);
}

// round 13
// speedup vs baseline: 1.2106x; 1.0239x over previous
#include <cuda_runtime.h>

#define N_IN       1024
#define BATCH      1024
#define DEG        32
#define TOTAL_COLS 18432
#define N_OUT      1024

// Unified int16 Q buffer, column-major: cols 0..1023 quantized input,
// cols 1024.. tanh outputs. Single dynamic scale g_s. 37.7 MB.
__device__ short g_q[(size_t)TOTAL_COLS * BATCH];
__device__ unsigned g_maxbits;
__device__ float g_s, g_is;

// PDL intrinsics (sm_90+)
__device__ __forceinline__ void pdl_wait() {
    asm volatile("griddepcontrol.wait;" ::: "memory");
}
__device__ __forceinline__ void pdl_launch_dependents() {
    asm volatile("griddepcontrol.launch_dependents;" ::: "memory");
}

__global__ void init_kernel() { g_maxbits = 0u; }

__global__ void maxabs_kernel(const float* __restrict__ X) {
    const float4* X4 = reinterpret_cast<const float4*>(X);
    float m = 0.f;
    for (int i = blockIdx.x * 256 + threadIdx.x; i < (N_IN * BATCH) / 4;
         i += gridDim.x * 256) {
        float4 v = X4[i];
        m = fmaxf(m, fmaxf(fmaxf(fabsf(v.x), fabsf(v.y)),
                           fmaxf(fabsf(v.z), fabsf(v.w))));
    }
    #pragma unroll
    for (int o = 16; o; o >>= 1)
        m = fmaxf(m, __shfl_xor_sync(0xFFFFFFFFu, m, o));
    if ((threadIdx.x & 31) == 0)
        atomicMax(&g_maxbits, __float_as_uint(m));  // non-neg floats: bit order = value order
}

__global__ void scale_kernel() {
    float m = __uint_as_float(g_maxbits);
    if (m < 1.0f) m = 1.0f;          // tanh outputs (|v|<1) must also fit
    float s = 32000.0f / m;
    g_s = s;
    g_is = 1.0f / s;
}

// ---------------------------------------------------------------------------
// Transpose X -> g_q cols 0..1023 (int16), ILP-4: each block handles 4
// stacked 32x32 tiles, 16 front-batched LDGs/thread (X is L2-hot after
// maxabs; 4x MLP hides latency). Direct int16 write, no staging.
// grid 256, block (32,8). PDL: X reads overlap scale tail; g_s after wait.
// ---------------------------------------------------------------------------
__global__ void transpose_in_kernel(const float* __restrict__ X) {
    __shared__ float tile[32][33];
    const int tx = threadIdx.x, ty = threadIdx.y;
    const int bx  = (blockIdx.x & 31) * 32;   // feature tile base
    const int by0 = (blockIdx.x >> 5) * 128;  // batch super-tile base

    float v[4][4];
    #pragma unroll
    for (int r = 0; r < 4; r++)
        #pragma unroll
        for (int i = 0; i < 4; i++)
            v[r][i] = X[(by0 + r * 32 + ty + i * 8) * N_IN + (bx + tx)];

    pdl_wait();                       // g_s valid after scale_kernel completes
    const float s = g_s;

    #pragma unroll
    for (int r = 0; r < 4; r++) {
        __syncthreads();
        #pragma unroll
        for (int i = 0; i < 4; i++)
            tile[ty + i * 8][tx] = v[r][i];
        __syncthreads();
        #pragma unroll
        for (int i = 0; i < 4; i++)
            g_q[(size_t)(bx + ty + i * 8) * BATCH + (by0 + r * 32 + tx)] =
                (short)__float2int_rn(tile[tx][ty + i * 8] * s);
    }
    pdl_launch_dependents();
}

// ---------------------------------------------------------------------------
// Gather core: 128 threads, thread t owns batch elems 8t..8t+7 (one uint4 =
// 8 int16). Exact integer accumulation via DP2A.
// ---------------------------------------------------------------------------
__device__ __forceinline__ void gather_sum(const int* __restrict__ sidx, int t,
                                           int acc[8]) {
    const uint4* q4 = reinterpret_cast<const uint4*>(g_q);
    int a0=0,a1=0,a2=0,a3=0,a4=0,a5=0,a6=0,a7=0;
    #pragma unroll
    for (int k = 0; k < DEG; k++) {
        uint4 v = q4[(size_t)sidx[k] * (BATCH / 8) + t];
        a0 = __dp2a_lo((int)v.x, 0x0001, a0);
        a1 = __dp2a_lo((int)v.x, 0x0100, a1);
        a2 = __dp2a_lo((int)v.y, 0x0001, a2);
        a3 = __dp2a_lo((int)v.y, 0x0100, a3);
        a4 = __dp2a_lo((int)v.z, 0x0001, a4);
        a5 = __dp2a_lo((int)v.z, 0x0100, a5);
        a6 = __dp2a_lo((int)v.w, 0x0001, a6);
        a7 = __dp2a_lo((int)v.w, 0x0100, a7);
    }
    acc[0]=a0; acc[1]=a1; acc[2]=a2; acc[3]=a3;
    acc[4]=a4; acc[5]=a5; acc[6]=a6; acc[7]=a7;
}

// ---------------------------------------------------------------------------
// Layers 1..8: preamble (index load) overlaps predecessor tail via PDL;
// dependents released right after the column store. (Byte-identical to R12.)
// ---------------------------------------------------------------------------
__global__ void __launch_bounds__(128) layer_kernel(
    const int* __restrict__ child_idx, const float* __restrict__ w_ptr,
    int col_base)
{
    const int j = blockIdx.x, t = threadIdx.x;
    __shared__ int sidx[DEG];
    if (t < DEG) sidx[t] = child_idx[j * DEG + t];   // input-only: pre-wait OK
    __syncthreads();
    pdl_wait();                        // predecessor's g_q writes now visible

    int a[8];
    gather_sum(sidx, t, a);

    const float w = __ldg(w_ptr), is = g_is, s = g_s;
    const float ws = w * is;

    int q[8];
    #pragma unroll
    for (int i = 0; i < 8; i++)
        q[i] = __float2int_rn(tanhf(ws * (float)a[i]) * s);

    uint4 o;
    o.x = (q[0] & 0xFFFF) | (q[1] << 16);
    o.y = (q[2] & 0xFFFF) | (q[3] << 16);
    o.z = (q[4] & 0xFFFF) | (q[5] << 16);
    o.w = (q[6] & 0xFFFF) | (q[7] << 16);
    reinterpret_cast<uint4*>(g_q)[(size_t)(col_base + j) * (BATCH / 8) + t] = o;

    pdl_launch_dependents();           // release next layer before block exit
}

// ---------------------------------------------------------------------------
// Layer 9: outputs never gathered -> write fp32 straight to d_out (row-major).
// ---------------------------------------------------------------------------
__global__ void __launch_bounds__(128) last_layer_kernel(
    const int* __restrict__ child_idx, const float* __restrict__ w_ptr,
    float* __restrict__ out)
{
    const int j = blockIdx.x, t = threadIdx.x;
    __shared__ int sidx[DEG];
    if (t < DEG) sidx[t] = child_idx[j * DEG + t];
    __syncthreads();
    pdl_wait();

    int a[8];
    gather_sum(sidx, t, a);

    const float w = __ldg(w_ptr), is = g_is;
    const float ws = w * is;

    #pragma unroll
    for (int i = 0; i < 8; i++)
        out[(size_t)(8 * t + i) * N_OUT + j] = tanhf(ws * (float)a[i]);
}

// ---------------------------------------------------------------------------
// Host-side PDL launch helper.
// ---------------------------------------------------------------------------
template <typename... Args>
static void launch_pdl(void (*kern)(Args...), dim3 grid, dim3 block,
                       Args... args) {
    cudaLaunchConfig_t cfg = {};
    cfg.gridDim = grid;
    cfg.blockDim = block;
    cfg.dynamicSmemBytes = 0;
    cfg.stream = 0;
    cudaLaunchAttribute attr[1];
    attr[0].id = cudaLaunchAttributeProgrammaticStreamSerialization;
    attr[0].val.programmaticStreamSerializationAllowed = 1;
    cfg.attrs = attr;
    cfg.numAttrs = 1;
    cudaLaunchKernelEx(&cfg, kern, args...);
}

extern "C" void kernel_launch(void* const* d_in, const int* in_sizes, int n_in,
                              void* d_out, int out_size) {
    const float* X         = (const float*)d_in[0];
    const float* w         = (const float*)d_in[1];
    const int*   child_idx = (const int*)d_in[2];
    float*       out       = (float*)d_out;
    (void)in_sizes; (void)n_in; (void)out_size;

    init_kernel<<<1, 1>>>();
    maxabs_kernel<<<148, 256>>>(X);
    scale_kernel<<<1, 1>>>();

    launch_pdl(transpose_in_kernel, dim3(256), dim3(32, 8), X);

    int idx_base = 0;
    int col_base = N_IN;
    for (int li = 0; li < 8; li++) {
        launch_pdl(layer_kernel, dim3(2048), dim3(128),
                   (const int*)(child_idx + (size_t)idx_base * DEG), w, col_base);
        idx_base += 2048;
        col_base += 2048;
    }
    launch_pdl(last_layer_kernel, dim3(1024), dim3(128),
               (const int*)(child_idx + (size_t)idx_base * DEG), w, out);
}